// round 1
// baseline (speedup 1.0000x reference)
#include <cuda_runtime.h>
#include <cstdint>

// Problem constants (from reference)
#define NS 2
#define NB 8
#define NC 32
#define NH 128
#define NW 128
#define NM 32
#define RH 64
#define RW 64

// Output layout: (n, b*M+m, c, r, w)  -> total rows of RW floats:
//   NS * (NB*NM) * NC * RH = 2*256*32*64 = 1,048,576 rows
// Each block: 256 threads = 16 rows x 16 threads; each thread stores one float4.
// All 16 rows in a block share the same (n, b, m) -> one box per block.

__global__ __launch_bounds__(256) void roi_patch_kernel(
    const float* __restrict__ fm,
    const int*   __restrict__ boxes,
    float*       __restrict__ out)
{
    const int rowBase = blockIdx.x << 4;          // 16 rows per block
    const int local   = threadIdx.x >> 4;         // 0..15 (row within block)
    const int lane16  = threadIdx.x & 15;         // 0..15 (float4 within row)
    const int row     = rowBase + local;

    // Decode row -> (n, bm, c, r). Row = ((n*256 + bm)*32 + c)*64 + r
    const int r  = row & 63;
    const int c  = (row >> 6) & 31;
    const int bm = (row >> 11) & 255;
    const int n  = row >> 19;
    const int b  = bm >> 5;
    const int m  = bm & 31;

    __shared__ int4 sbox;
    if (threadIdx.x == 0) {
        const int bi = ((n * NB + b) * NM + m) * 4;
        sbox = *reinterpret_cast<const int4*>(boxes + bi);
    }
    __syncthreads();

    const int x1   = sbox.x;
    const int y1   = sbox.y;
    const int wbox = sbox.z - x1;   // box width  (cols valid: cc < wbox)
    const int hbox = sbox.w - y1;   // box height (rows valid: r  < hbox)

    float4 v = make_float4(0.f, 0.f, 0.f, 0.f);

    if (r < hbox) {
        const int srow = min(y1 + r, NH - 1);  // never clips per setup; cheap safety
        const float* __restrict__ src =
            fm + ((((size_t)(n * NB + b)) * NC + c) * NH + srow) * NW;
        const int c0 = lane16 << 2;
        float tmp[4];
        #pragma unroll
        for (int j = 0; j < 4; ++j) {
            const int cc = c0 + j;
            tmp[j] = 0.f;
            if (cc < wbox) {
                const int scol = min(x1 + cc, NW - 1);
                tmp[j] = __ldg(src + scol);
            }
        }
        v.x = tmp[0]; v.y = tmp[1]; v.z = tmp[2]; v.w = tmp[3];
    }

    // Contiguous, 16B-aligned store
    const size_t oidx = ((size_t)row << 6) + ((size_t)lane16 << 2);
    *reinterpret_cast<float4*>(out + oidx) = v;
}

extern "C" void kernel_launch(void* const* d_in, const int* in_sizes, int n_in,
                              void* d_out, int out_size)
{
    const float* fm    = (const float*)d_in[0];
    const int*   boxes = (const int*)d_in[1];
    float*       out   = (float*)d_out;

    // Total rows = NS * NB * NM * NC * RH = 1,048,576; 16 rows/block
    const int total_rows = NS * NB * NM * NC * RH;
    const int blocks = total_rows / 16;   // 65,536
    roi_patch_kernel<<<blocks, 256>>>(fm, boxes, out);
}

// round 2
// speedup vs baseline: 1.4039x; 1.4039x over previous
#include <cuda_runtime.h>
#include <cstdint>

// Problem constants
#define NS 2
#define NB 8
#define NC 32
#define NH 128
#define NW 128
#define NM 32
#define RH 64
#define RW 64

// One block = one (n, bm, c) output tile of 64x64 floats (16 KB).
// 256 threads; each thread writes 4 float4s at rows r0, r0+16, r0+32, r0+48.
// blockIdx.x = ((n*256 + bm) * 32 + c)  -> output offset = blockIdx.x * 4096.

__global__ __launch_bounds__(256) void roi_patch_kernel(
    const float* __restrict__ fm,
    const int*   __restrict__ boxes,
    float*       __restrict__ out)
{
    const int blk = blockIdx.x;
    const int c   = blk & 31;
    const int bm  = (blk >> 5) & 255;
    const int n   = blk >> 13;
    const int b   = bm >> 5;
    const int m   = bm & 31;

    __shared__ int4 sbox;
    if (threadIdx.x == 0) {
        sbox = reinterpret_cast<const int4*>(boxes)[(n * NB + b) * NM + m];
    }
    __syncthreads();

    const int x1   = sbox.x;
    const int y1   = sbox.y;
    const int wbox = sbox.z - x1;   // valid cols: cc < wbox  (8..64)
    const int hbox = sbox.w - y1;   // valid rows: r  < hbox  (8..64)

    const int lane16 = threadIdx.x & 15;
    const int r0     = threadIdx.x >> 4;     // 0..15
    const int c0     = lane16 << 2;

    // Per-setup guarantees: x1 + cc <= 127 and y1 + r <= 127 whenever the
    // mask is live (x1 <= W-ROI_W, cc < wbox <= ROI_W) -> no clamping needed.
    const bool v0 = (c0 + 0) < wbox;
    const bool v1 = (c0 + 1) < wbox;
    const bool v2 = (c0 + 2) < wbox;
    const bool v3 = (c0 + 3) < wbox;

    const float* src = fm
        + (((size_t)(n * NB + b) * NC + c) * NH + (y1 + r0)) * NW
        + (x1 + c0);
    float* dst = out + ((size_t)blk << 12) + (r0 << 6) + c0;

    #pragma unroll
    for (int i = 0; i < 4; ++i) {
        const int r = r0 + (i << 4);
        float4 val = make_float4(0.f, 0.f, 0.f, 0.f);
        if (r < hbox) {
            const float* s = src + (size_t)(i << 4) * NW;
            if (v0) val.x = __ldg(s + 0);
            if (v1) val.y = __ldg(s + 1);
            if (v2) val.z = __ldg(s + 2);
            if (v3) val.w = __ldg(s + 3);
        }
        // Streaming store: output is write-once; keep fm resident in L2.
        __stcs(reinterpret_cast<float4*>(dst + ((size_t)(i << 4) << 6)), val);
    }
}

extern "C" void kernel_launch(void* const* d_in, const int* in_sizes, int n_in,
                              void* d_out, int out_size)
{
    const float* fm    = (const float*)d_in[0];
    const int*   boxes = (const int*)d_in[1];
    float*       out   = (float*)d_out;

    const int blocks = NS * NB * NM * NC;   // 16384 tiles
    roi_patch_kernel<<<blocks, 256>>>(fm, boxes, out);
}

// round 3
// speedup vs baseline: 1.4441x; 1.0286x over previous
#include <cuda_runtime.h>
#include <cstdint>

#define NS 2
#define NB 8
#define NC 32
#define NH 128
#define NW 128
#define NM 32
#define RH 64
#define RW 64

// One block = one (n, bm, c) output tile of 64x64 floats (16 KB).
// 256 threads; each thread writes 4 float4s at rows r0, r0+16, r0+32, r0+48.
// x1 alignment (off = x1 & 3) is block-uniform -> compile-time-shift bodies.

template <int OFF>
__device__ __forceinline__ void tile_body(
    const float* __restrict__ srcA,   // aligned: plane + (y1+r0)*NW + (x1-OFF) + c0
    float* __restrict__ dst,          // out tile + r0*64 + c0
    int r0, int c0, int hbox, int wbox)
{
    const bool cv  = c0 < wbox;        // any column of this float4 valid
    const bool m1  = (c0 + 1) < wbox;
    const bool m2  = (c0 + 2) < wbox;
    const bool m3  = (c0 + 3) < wbox;

    #pragma unroll
    for (int i = 0; i < 4; ++i) {
        const int r = r0 + (i << 4);
        float4 val = make_float4(0.f, 0.f, 0.f, 0.f);
        if (r < hbox && cv) {
            const float4* p = reinterpret_cast<const float4*>(srcA + (i << 4) * NW);
            const float4 A = __ldg(p);
            if (OFF == 0) {
                val = A;
            } else {
                const float4 B = __ldg(p + 1);
                if (OFF == 1) val = make_float4(A.y, A.z, A.w, B.x);
                if (OFF == 2) val = make_float4(A.z, A.w, B.x, B.y);
                if (OFF == 3) val = make_float4(A.w, B.x, B.y, B.z);
            }
            if (!m1) val.y = 0.f;
            if (!m2) val.z = 0.f;
            if (!m3) val.w = 0.f;
        }
        __stcs(reinterpret_cast<float4*>(dst + ((i << 4) << 6)), val);
    }
}

__global__ __launch_bounds__(256) void roi_patch_kernel(
    const float* __restrict__ fm,
    const int*   __restrict__ boxes,
    float*       __restrict__ out)
{
    const int blk = blockIdx.x;
    const int c   = blk & 31;
    const int bm  = (blk >> 5) & 255;
    const int n   = blk >> 13;
    const int b   = bm >> 5;
    const int m   = bm & 31;

    __shared__ int4 sbox;
    if (threadIdx.x == 0) {
        sbox = reinterpret_cast<const int4*>(boxes)[(n * NB + b) * NM + m];
    }
    __syncthreads();

    const int x1   = sbox.x;
    const int y1   = sbox.y;
    const int wbox = sbox.z - x1;   // valid cols: cc < wbox  (8..64)
    const int hbox = sbox.w - y1;   // valid rows: r  < hbox  (8..64)
    const int off  = x1 & 3;        // block-uniform

    const int lane16 = threadIdx.x & 15;
    const int r0     = threadIdx.x >> 4;     // 0..15
    const int c0     = lane16 << 2;

    const float* srcA = fm
        + (((size_t)(n * NB + b) * NC + c) * NH + (y1 + r0)) * NW
        + (x1 - off) + c0;                   // 16B-aligned
    float* dst = out + ((size_t)blk << 12) + (r0 << 6) + c0;

    switch (off) {
        case 0: tile_body<0>(srcA, dst, r0, c0, hbox, wbox); break;
        case 1: tile_body<1>(srcA, dst, r0, c0, hbox, wbox); break;
        case 2: tile_body<2>(srcA, dst, r0, c0, hbox, wbox); break;
        default: tile_body<3>(srcA, dst, r0, c0, hbox, wbox); break;
    }
}

extern "C" void kernel_launch(void* const* d_in, const int* in_sizes, int n_in,
                              void* d_out, int out_size)
{
    const float* fm    = (const float*)d_in[0];
    const int*   boxes = (const int*)d_in[1];
    float*       out   = (float*)d_out;

    const int blocks = NS * NB * NM * NC;   // 16384 tiles
    roi_patch_kernel<<<blocks, 256>>>(fm, boxes, out);
}